// round 9
// baseline (speedup 1.0000x reference)
#include <cuda_runtime.h>
#include <cuda_bf16.h>
#include <cuda_fp16.h>
#include <math.h>
#include <stdint.h>

#define BATCH 8
#define CIN   256
#define CI    128
#define NPOS  4096

// ---------------- scratch (allocation-free: __device__ globals) ----------------
__device__ __align__(16) __nv_bfloat16 g_Xh [(size_t)BATCH * CIN * NPOS];  // x hi [b][c][n]
__device__ __align__(16) __nv_bfloat16 g_Xl [(size_t)BATCH * CIN * NPOS];
__device__ __align__(16) __nv_bfloat16 g_THh[(size_t)BATCH * NPOS * CI];   // theta [b][n][c]
__device__ __align__(16) __nv_bfloat16 g_THl[(size_t)BATCH * NPOS * CI];
__device__ __align__(16) __nv_bfloat16 g_PHh[(size_t)BATCH * NPOS * CI];   // phi   [b][n][c]
__device__ __align__(16) __nv_bfloat16 g_PHl[(size_t)BATCH * NPOS * CI];
__device__ __align__(16) __half        g_G  [(size_t)BATCH * CI * NPOS];   // g fp16 [b][c][n]
__device__ __align__(16) __nv_bfloat16 g_WQh[2 * CI * CIN];   // [theta_w ; phi_w]
__device__ __align__(16) __nv_bfloat16 g_WQl[2 * CI * CIN];
__device__ __align__(16) __nv_bfloat16 g_WGh[CI * CIN];       // g_w [128][256]
__device__ __align__(16) __nv_bfloat16 g_WGl[CI * CIN];
__device__ __align__(16) __half        g_Whalf[CIN * CI];     // W_w fp16 [256][128]
__device__ float g_WY[(size_t)BATCH * CIN * NPOS];            // W(y) [b][o][n]
__device__ float g_ps[4 * CIN], g_pss[4 * CIN];
__device__ float g_mean[CIN];
__device__ float g_rstd[CIN];

// ---------------- helpers ----------------
__device__ __forceinline__ uint32_t s2u(const void* p) {
    uint32_t a;
    asm("{ .reg .u64 t; cvta.to.shared.u64 t, %1; cvt.u32.u64 %0, t; }" : "=r"(a) : "l"(p));
    return a;
}
__device__ __forceinline__ void ldsm4(uint32_t r[4], uint32_t addr) {
    asm volatile("ldmatrix.sync.aligned.m8n8.x4.shared.b16 {%0,%1,%2,%3}, [%4];"
                 : "=r"(r[0]), "=r"(r[1]), "=r"(r[2]), "=r"(r[3]) : "r"(addr));
}
__device__ __forceinline__ void ldsm4t(uint32_t r[4], uint32_t addr) {
    asm volatile("ldmatrix.sync.aligned.m8n8.x4.trans.shared.b16 {%0,%1,%2,%3}, [%4];"
                 : "=r"(r[0]), "=r"(r[1]), "=r"(r[2]), "=r"(r[3]) : "r"(addr));
}
__device__ __forceinline__ void mma16816(float d[4], const uint32_t a[4],
                                         uint32_t b0, uint32_t b1) {
    asm volatile(
        "mma.sync.aligned.m16n8k16.row.col.f32.bf16.bf16.f32 "
        "{%0,%1,%2,%3}, {%4,%5,%6,%7}, {%8,%9}, {%0,%1,%2,%3};"
        : "+f"(d[0]), "+f"(d[1]), "+f"(d[2]), "+f"(d[3])
        : "r"(a[0]), "r"(a[1]), "r"(a[2]), "r"(a[3]), "r"(b0), "r"(b1));
}
__device__ __forceinline__ void mma16816h(float d[4], const uint32_t a[4],
                                          uint32_t b0, uint32_t b1) {
    asm volatile(
        "mma.sync.aligned.m16n8k16.row.col.f32.f16.f16.f32 "
        "{%0,%1,%2,%3}, {%4,%5,%6,%7}, {%8,%9}, {%0,%1,%2,%3};"
        : "+f"(d[0]), "+f"(d[1]), "+f"(d[2]), "+f"(d[3])
        : "r"(a[0]), "r"(a[1]), "r"(a[2]), "r"(a[3]), "r"(b0), "r"(b1));
}
__device__ __forceinline__ void cpa16(uint32_t dst, const void* src) {
    asm volatile("cp.async.cg.shared.global [%0], [%1], 16;" :: "r"(dst), "l"(src));
}
#define CP_COMMIT() asm volatile("cp.async.commit_group;" ::: "memory")
#define CP_WAIT0()  asm volatile("cp.async.wait_group 0;" ::: "memory")
#define CP_WAIT1()  asm volatile("cp.async.wait_group 1;" ::: "memory")

// fast packed bf16 split
__device__ __forceinline__ uint32_t pkbf(float a, float b, float* ra, float* rb) {
    __nv_bfloat162 h2 = __floats2bfloat162_rn(a, b);   // .x = a (low)
    uint32_t u = *reinterpret_cast<uint32_t*>(&h2);
    *ra = a - __uint_as_float(u << 16);
    *rb = b - __uint_as_float(u & 0xffff0000u);
    return u;
}
__device__ __forceinline__ uint32_t pkbf2(float a, float b) {
    __nv_bfloat162 h2 = __floats2bfloat162_rn(a, b);
    return *reinterpret_cast<uint32_t*>(&h2);
}
__device__ __forceinline__ uint32_t pkh2(float a, float b) {
    __half2 h2 = __floats2half2_rn(a, b);
    return *reinterpret_cast<uint32_t*>(&h2);
}

// =================================================================
// K0a: split x -> bf16 hi/lo
// =================================================================
__global__ __launch_bounds__(256) void split_x_kernel(const float* __restrict__ x)
{
    size_t i = ((size_t)blockIdx.x * 256 + threadIdx.x) * 4;
    float4 v = *(const float4*)&x[i];
    float r0, r1, r2, r3;
    uint32_t h01 = pkbf(v.x, v.y, &r0, &r1);
    uint32_t h23 = pkbf(v.z, v.w, &r2, &r3);
    *(uint2*)&g_Xh[i] = make_uint2(h01, h23);
    *(uint2*)&g_Xl[i] = make_uint2(pkbf2(r0, r1), pkbf2(r2, r3));
}

// =================================================================
// K0b: split weights (theta/phi/g -> bf16 hi/lo, W -> fp16 single)
// =================================================================
__global__ __launch_bounds__(256) void split_wts_kernel(
    const float* __restrict__ thw, const float* __restrict__ phw,
    const float* __restrict__ gw,  const float* __restrict__ Ww)
{
    int i = blockIdx.x * 256 + threadIdx.x;   // 0..131071
    int which = i >> 15, j = i & 32767;
    if (which == 3) { g_Whalf[j] = __float2half(Ww[j]); return; }
    float v;
    __nv_bfloat16 *dh, *dl;
    int o;
    if (which == 0)      { v = thw[j]; dh = g_WQh; dl = g_WQl; o = j; }
    else if (which == 1) { v = phw[j]; dh = g_WQh; dl = g_WQl; o = 32768 + j; }
    else                 { v = gw[j];  dh = g_WGh; dl = g_WGl; o = j; }
    __nv_bfloat16 h = __float2bfloat16(v);
    dh[o] = h;
    dl[o] = __float2bfloat16(v - __bfloat162float(h));
}

// =================================================================
// K1a: theta/phi projection (HMMA, bf16 split) -> [b][n][c] hi/lo
// =================================================================
#define PSQ 272
#define PSW 80
#define PJ_XH 0
#define PJ_XL 8704
#define PJ_WH 17408
#define PJ_WL 37888
#define PJ_BUF 58368
#define PJ_BIAS 116736
#define PJ_SMEM 117760

__global__ __launch_bounds__(256, 1) void proj_npos_kernel(
    const float* __restrict__ th_b, const float* __restrict__ ph_b)
{
    extern __shared__ __align__(16) char smem[];
    const uint32_t sb = s2u(smem);
    const int t = threadIdx.x, w = t >> 5, L = t & 31;
    const int g = L >> 2, tc = L & 3;
    const int b = blockIdx.y;
    const int n0 = blockIdx.x * 128;

    float* bias = (float*)(smem + PJ_BIAS);
    bias[t] = (t < 128) ? th_b[t] : ph_b[t - 128];

    const __nv_bfloat16* xh = g_Xh + (size_t)b * CIN * NPOS + n0;
    const __nv_bfloat16* xl = g_Xl + (size_t)b * CIN * NPOS + n0;

    const uint32_t aoff = (uint32_t)(((L & 7) + ((L >> 4) & 1) * 8) * PSQ + 32 * w +
                                     ((L >> 3) & 1) * 16);
    const uint32_t boff = (uint32_t)(((L >> 4) * 8 + (L & 7)) * PSW + ((L >> 3) & 1) * 16);

    float acc[32][4];
    #pragma unroll
    for (int j = 0; j < 32; j++)
        #pragma unroll
        for (int k = 0; k < 4; k++) acc[j][k] = 0.f;

    {
        uint32_t base = sb;
        for (int i = t; i < 512; i += 256) {
            int r = i >> 4, c16 = i & 15;
            uint32_t doff = (uint32_t)(r * PSQ + c16 * 16);
            cpa16(base + PJ_XH + doff, xh + (size_t)r * NPOS + c16 * 8);
            cpa16(base + PJ_XL + doff, xl + (size_t)r * NPOS + c16 * 8);
        }
        for (int i = t; i < 1024; i += 256) {
            int r = i >> 2, c4 = i & 3;
            uint32_t doff = (uint32_t)(r * PSW + c4 * 16);
            cpa16(base + PJ_WH + doff, g_WQh + (size_t)r * CIN + c4 * 8);
            cpa16(base + PJ_WL + doff, g_WQl + (size_t)r * CIN + c4 * 8);
        }
        CP_COMMIT();
    }

    #pragma unroll 1
    for (int ch = 0; ch < 8; ch++) {
        if (ch < 7) {
            int c0 = (ch + 1) * 32;
            uint32_t base = sb + ((ch + 1) & 1) * PJ_BUF;
            for (int i = t; i < 512; i += 256) {
                int r = i >> 4, c16 = i & 15;
                uint32_t doff = (uint32_t)(r * PSQ + c16 * 16);
                cpa16(base + PJ_XH + doff, xh + (size_t)(c0 + r) * NPOS + c16 * 8);
                cpa16(base + PJ_XL + doff, xl + (size_t)(c0 + r) * NPOS + c16 * 8);
            }
            for (int i = t; i < 1024; i += 256) {
                int r = i >> 2, c4 = i & 3;
                uint32_t doff = (uint32_t)(r * PSW + c4 * 16);
                cpa16(base + PJ_WH + doff, g_WQh + (size_t)r * CIN + c0 + c4 * 8);
                cpa16(base + PJ_WL + doff, g_WQl + (size_t)r * CIN + c0 + c4 * 8);
            }
            CP_COMMIT();
            CP_WAIT1();
        } else {
            CP_WAIT0();
        }
        __syncthreads();
        const uint32_t xbase = sb + (ch & 1) * PJ_BUF;
        const uint32_t aB = xbase + PJ_XH + aoff;
        const uint32_t bB = xbase + PJ_WH + boff;
        #pragma unroll
        for (int kk = 0; kk < 2; kk++) {
            uint32_t ah[4], al[4];
            ldsm4t(ah, aB + kk * 16 * PSQ);
            ldsm4t(al, aB + 8704 + kk * 16 * PSQ);
            #pragma unroll
            for (int np = 0; np < 16; np++) {
                uint32_t bh[4], bl[4];
                ldsm4(bh, bB + np * (16 * PSW) + kk * 32);
                ldsm4(bl, bB + 20480 + np * (16 * PSW) + kk * 32);
                mma16816(acc[2 * np],     ah, bh[0], bh[1]);
                mma16816(acc[2 * np + 1], ah, bh[2], bh[3]);
                mma16816(acc[2 * np],     ah, bl[0], bl[1]);
                mma16816(acc[2 * np + 1], ah, bl[2], bl[3]);
                mma16816(acc[2 * np],     al, bh[0], bh[1]);
                mma16816(acc[2 * np + 1], al, bh[2], bh[3]);
            }
        }
        __syncthreads();
    }

    const int nrow = n0 + 16 * w + g;
    const size_t rb0 = ((size_t)b * NPOS + nrow) * CI;
    const size_t rb1 = rb0 + (size_t)8 * CI;
    #pragma unroll
    for (int j = 0; j < 32; j++) {
        int o = 8 * j + 2 * tc;
        float b0 = bias[o], b1 = bias[o + 1];
        __nv_bfloat16 *dh, *dl;
        int c;
        if (o < 128) { dh = g_THh; dl = g_THl; c = o; }
        else         { dh = g_PHh; dl = g_PHl; c = o - 128; }
        float r0, r1;
        uint32_t hp = pkbf(acc[j][0] + b0, acc[j][1] + b1, &r0, &r1);
        uint32_t lp = pkbf2(r0, r1);
        *(uint32_t*)(dh + rb0 + c) = hp;
        *(uint32_t*)(dl + rb0 + c) = lp;
        hp = pkbf(acc[j][2] + b0, acc[j][3] + b1, &r0, &r1);
        lp = pkbf2(r0, r1);
        *(uint32_t*)(dh + rb1 + c) = hp;
        *(uint32_t*)(dl + rb1 + c) = lp;
    }
}

// =================================================================
// K1b: g projection (HMMA, bf16 split compute) -> fp16 single [b][c][n]
// occupancy 2 (regs capped at 127) for latency hiding.
// =================================================================
#define PG_XH 0
#define PG_XL 8704
#define PG_WH 17408
#define PG_WL 27648
#define PG_BUF 37888
#define PG_BIAS 75776
#define PG_SMEM 76800

__global__ __launch_bounds__(256, 2) void proj_chan_kernel(const float* __restrict__ g_b)
{
    extern __shared__ __align__(16) char smem[];
    const uint32_t sb = s2u(smem);
    const int t = threadIdx.x, w = t >> 5, L = t & 31;
    const int g = L >> 2, tc = L & 3;
    const int b = blockIdx.y;
    const int n0 = blockIdx.x * 128;

    float* bias = (float*)(smem + PG_BIAS);
    if (t < 128) bias[t] = g_b[t];

    const __nv_bfloat16* xh = g_Xh + (size_t)b * CIN * NPOS + n0;
    const __nv_bfloat16* xl = g_Xl + (size_t)b * CIN * NPOS + n0;

    const uint32_t aoff = (uint32_t)((16 * w + (L & 7) + ((L >> 3) & 1) * 8) * PSW +
                                     (L >> 4) * 16);
    const uint32_t boff = (uint32_t)(((L & 7) + ((L >> 3) & 1) * 8) * PSQ + (L >> 4) * 16);

    float acc[16][4];
    #pragma unroll
    for (int j = 0; j < 16; j++)
        #pragma unroll
        for (int k = 0; k < 4; k++) acc[j][k] = 0.f;

    {
        uint32_t base = sb;
        for (int i = t; i < 512; i += 256) {
            int r = i >> 4, c16 = i & 15;
            uint32_t doff = (uint32_t)(r * PSQ + c16 * 16);
            cpa16(base + PG_XH + doff, xh + (size_t)r * NPOS + c16 * 8);
            cpa16(base + PG_XL + doff, xl + (size_t)r * NPOS + c16 * 8);
        }
        for (int i = t; i < 512; i += 256) {
            int r = i >> 2, c4 = i & 3;
            uint32_t doff = (uint32_t)(r * PSW + c4 * 16);
            cpa16(base + PG_WH + doff, g_WGh + (size_t)r * CIN + c4 * 8);
            cpa16(base + PG_WL + doff, g_WGl + (size_t)r * CIN + c4 * 8);
        }
        CP_COMMIT();
    }

    #pragma unroll 1
    for (int ch = 0; ch < 8; ch++) {
        if (ch < 7) {
            int c0 = (ch + 1) * 32;
            uint32_t base = sb + ((ch + 1) & 1) * PG_BUF;
            for (int i = t; i < 512; i += 256) {
                int r = i >> 4, c16 = i & 15;
                uint32_t doff = (uint32_t)(r * PSQ + c16 * 16);
                cpa16(base + PG_XH + doff, xh + (size_t)(c0 + r) * NPOS + c16 * 8);
                cpa16(base + PG_XL + doff, xl + (size_t)(c0 + r) * NPOS + c16 * 8);
            }
            for (int i = t; i < 512; i += 256) {
                int r = i >> 2, c4 = i & 3;
                uint32_t doff = (uint32_t)(r * PSW + c4 * 16);
                cpa16(base + PG_WH + doff, g_WGh + (size_t)r * CIN + c0 + c4 * 8);
                cpa16(base + PG_WL + doff, g_WGl + (size_t)r * CIN + c0 + c4 * 8);
            }
            CP_COMMIT();
            CP_WAIT1();
        } else {
            CP_WAIT0();
        }
        __syncthreads();
        const uint32_t xbase = sb + (ch & 1) * PG_BUF;
        const uint32_t aB = xbase + PG_WH + aoff;
        const uint32_t bB = xbase + PG_XH + boff;
        #pragma unroll
        for (int kk = 0; kk < 2; kk++) {
            uint32_t ah[4], al[4];
            ldsm4(ah, aB + kk * 32);
            ldsm4(al, aB + 10240 + kk * 32);
            #pragma unroll
            for (int np = 0; np < 8; np++) {
                uint32_t bh[4], bl[4];
                ldsm4t(bh, bB + np * 32 + kk * 16 * PSQ);
                ldsm4t(bl, bB + 8704 + np * 32 + kk * 16 * PSQ);
                mma16816(acc[2 * np],     ah, bh[0], bh[1]);
                mma16816(acc[2 * np + 1], ah, bh[2], bh[3]);
                mma16816(acc[2 * np],     ah, bl[0], bl[1]);
                mma16816(acc[2 * np + 1], ah, bl[2], bl[3]);
                mma16816(acc[2 * np],     al, bh[0], bh[1]);
                mma16816(acc[2 * np + 1], al, bh[2], bh[3]);
            }
        }
        __syncthreads();
    }

    const int o = 16 * w + g;
    const float b0 = bias[o], b8 = bias[o + 8];
    #pragma unroll
    for (int j = 0; j < 16; j++) {
        int n = 16 * (j >> 1) + 8 * (j & 1) + 2 * tc;
        size_t a0 = ((size_t)b * CI + o) * NPOS + n0 + n;
        size_t a8 = a0 + (size_t)8 * NPOS;
        *(uint32_t*)(g_G + a0) = pkh2(acc[j][0] + b0, acc[j][1] + b0);
        *(uint32_t*)(g_G + a8) = pkh2(acc[j][2] + b8, acc[j][3] + b8);
    }
}

// =================================================================
// K2: HMMA attention — QK bf16 3-term (Q frags resident in registers),
// PV fp16 1-term (flash online max, skip-rescale), W-conv fp16 1-term.
// =================================================================
#define SQ  272
#define SPG 144
#define SM_QH  0
#define SM_QL  34816
#define SM_K0  69632            // K buf0: hi @0, lo @+17408
#define SM_K1  104448           // K buf1
#define SM_G0  139264           // G buf0 (fp16 single)
#define SM_G1  157696           // G buf1
#define SMEM_BYTES 176128
#define SM_WB  69632            // epilogue: W fp16 tile aliases K0

__global__ __launch_bounds__(256, 1) void attn_mma_kernel(const float* __restrict__ W_b)
{
    extern __shared__ __align__(16) char smem[];
    const uint32_t sb = s2u(smem);
    const int t = threadIdx.x, w = t >> 5, L = t & 31;
    const int b = blockIdx.y;
    const int q0 = blockIdx.x * 128;
    const int g  = L >> 2, tc = L & 3;

    const __nv_bfloat16* qh  = g_THh + ((size_t)b * NPOS + q0) * CI;
    const __nv_bfloat16* ql  = g_THl + ((size_t)b * NPOS + q0) * CI;
    const __nv_bfloat16* khb = g_PHh + (size_t)b * NPOS * CI;
    const __nv_bfloat16* klb = g_PHl + (size_t)b * NPOS * CI;
    const __half*        ghb = g_G + (size_t)b * CI * NPOS;

    // prologue: Q, K(0)->buf0, G(0)->buf0 (one cp.async group)
    for (int i = t; i < 2048; i += 256) {
        int r = i >> 4, c16 = i & 15;
        uint32_t doff = (uint32_t)(r * SQ + c16 * 16);
        cpa16(sb + SM_QH + doff, qh + (size_t)r * CI + c16 * 8);
        cpa16(sb + SM_QL + doff, ql + (size_t)r * CI + c16 * 8);
    }
    for (int i = t; i < 1024; i += 256) {
        int r = i >> 4, c16 = i & 15;
        uint32_t doff = (uint32_t)(r * SQ + c16 * 16);
        cpa16(sb + SM_K0 + doff, khb + (size_t)r * CI + c16 * 8);
        cpa16(sb + SM_K0 + 17408 + doff, klb + (size_t)r * CI + c16 * 8);
    }
    for (int i = t; i < 1024; i += 256) {
        int r = i >> 3, c8 = i & 7;
        cpa16(sb + SM_G0 + (uint32_t)(r * SPG + c8 * 16), ghb + (size_t)r * NPOS + c8 * 8);
    }
    CP_COMMIT();

    // per-lane ldmatrix bases
    const int lr = ((L >> 3) & 1) * 8 + (L & 7);
    const int lk = (L >> 4) * 16;
    const int bn = (L >> 4) * 8 + (L & 7);
    const int bk = ((L >> 3) & 1) * 16;

    const uint32_t aQh = sb + SM_QH + (uint32_t)((16 * w + lr) * SQ + lk);
    const uint32_t aQl = aQh + (SM_QL - SM_QH);
    const uint32_t kOff = (uint32_t)(bn * SQ + bk);
    const uint32_t gOff = (uint32_t)(bn * SPG + bk);

    // wait for prologue, then hoist Q fragments into registers (resident)
    CP_WAIT0();
    __syncthreads();
    uint32_t qfh[8][4], qfl[8][4];
    #pragma unroll
    for (int kk = 0; kk < 8; kk++) {
        ldsm4(qfh[kk], aQh + kk * 32);
        ldsm4(qfl[kk], aQl + kk * 32);
    }

    float yacc[16][4];
    #pragma unroll
    for (int n = 0; n < 16; n++)
        #pragma unroll
        for (int j = 0; j < 4; j++) yacc[n][j] = 0.f;
    float ls0 = 0.f, ls1 = 0.f;
    float m0 = -INFINITY, m1 = -INFINITY;

    #pragma unroll 1
    for (int mt = 0; mt < NPOS / 64; mt++) {
        if (mt > 0) {
            CP_WAIT0();
            __syncthreads();   // K(mt),G(mt) ready; prev-buffer reads done
        }

        // prefetch K(mt+1), G(mt+1) into alternate buffers
        if (mt < 63) {
            const int m1i = mt * 64 + 64;
            const uint32_t kdst = sb + (((mt + 1) & 1) ? SM_K1 : SM_K0);
            const uint32_t gdst = sb + (((mt + 1) & 1) ? SM_G1 : SM_G0);
            for (int i = t; i < 1024; i += 256) {
                int r = i >> 4, c16 = i & 15;
                uint32_t doff = (uint32_t)(r * SQ + c16 * 16);
                cpa16(kdst + doff, khb + (size_t)(m1i + r) * CI + c16 * 8);
                cpa16(kdst + 17408 + doff, klb + (size_t)(m1i + r) * CI + c16 * 8);
            }
            for (int i = t; i < 1024; i += 256) {
                int r = i >> 3, c8 = i & 7;
                cpa16(gdst + (uint32_t)(r * SPG + c8 * 16),
                      ghb + (size_t)r * NPOS + m1i + c8 * 8);
            }
            CP_COMMIT();
        }

        // ---- QK fused-split (bf16, 3 terms); Q frags from registers ----
        const uint32_t bKh = sb + ((mt & 1) ? SM_K1 : SM_K0) + kOff;
        const uint32_t bKl = bKh + 17408;
        float acc[8][4];
        #pragma unroll
        for (int n = 0; n < 8; n++)
            #pragma unroll
            for (int j = 0; j < 4; j++) acc[n][j] = 0.f;
        #pragma unroll
        for (int kk = 0; kk < 8; kk++) {
            #pragma unroll
            for (int np = 0; np < 4; np++) {
                uint32_t bh[4], bl[4];
                ldsm4(bh, bKh + np * (16 * SQ) + kk * 32);
                ldsm4(bl, bKl + np * (16 * SQ) + kk * 32);
                mma16816(acc[2 * np],     qfh[kk], bh[0], bh[1]);
                mma16816(acc[2 * np + 1], qfh[kk], bh[2], bh[3]);
                mma16816(acc[2 * np],     qfh[kk], bl[0], bl[1]);
                mma16816(acc[2 * np + 1], qfh[kk], bl[2], bl[3]);
                mma16816(acc[2 * np],     qfl[kk], bh[0], bh[1]);
                mma16816(acc[2 * np + 1], qfl[kk], bh[2], bh[3]);
            }
        }

        // ---- flash online-max softmax ----
        float tm0 = -INFINITY, tm1 = -INFINITY;
        #pragma unroll
        for (int n = 0; n < 8; n++) {
            tm0 = fmaxf(tm0, fmaxf(acc[n][0], acc[n][1]));
            tm1 = fmaxf(tm1, fmaxf(acc[n][2], acc[n][3]));
        }
        tm0 = fmaxf(tm0, __shfl_xor_sync(0xffffffffu, tm0, 1));
        tm0 = fmaxf(tm0, __shfl_xor_sync(0xffffffffu, tm0, 2));
        tm1 = fmaxf(tm1, __shfl_xor_sync(0xffffffffu, tm1, 1));
        tm1 = fmaxf(tm1, __shfl_xor_sync(0xffffffffu, tm1, 2));
        bool noup = (tm0 <= m0) && (tm1 <= m1);
        if (!__all_sync(0xffffffffu, noup)) {
            float mn0 = fmaxf(m0, tm0), mn1 = fmaxf(m1, tm1);
            float al0 = __expf(m0 - mn0), al1 = __expf(m1 - mn1);
            m0 = mn0; m1 = mn1;
            ls0 *= al0; ls1 *= al1;
            #pragma unroll
            for (int n = 0; n < 16; n++) {
                yacc[n][0] *= al0; yacc[n][1] *= al0;
                yacc[n][2] *= al1; yacc[n][3] *= al1;
            }
        }

        // exp + pack P directly into fp16 A-fragments
        uint32_t pf[4][4];
        #pragma unroll
        for (int n = 0; n < 8; n++) {
            float p0 = __expf(acc[n][0] - m0);
            float p1 = __expf(acc[n][1] - m0);
            float p2 = __expf(acc[n][2] - m1);
            float p3 = __expf(acc[n][3] - m1);
            ls0 += p0 + p1;
            ls1 += p2 + p3;
            int kk = n >> 1, e = (n & 1) * 2;
            pf[kk][e]     = pkh2(p0, p1);
            pf[kk][e + 1] = pkh2(p2, p3);
        }

        // ---- PV (fp16 single term) ----
        const uint32_t bG = sb + ((mt & 1) ? SM_G1 : SM_G0) + gOff;
        #pragma unroll
        for (int kk = 0; kk < 4; kk++) {
            #pragma unroll
            for (int np = 0; np < 8; np++) {
                uint32_t bh[4];
                ldsm4(bh, bG + np * (16 * SPG) + kk * 32);
                mma16816h(yacc[2 * np],     pf[kk], bh[0], bh[1]);
                mma16816h(yacc[2 * np + 1], pf[kk], bh[2], bh[3]);
            }
        }
    }

    // ---- finalize row sums ----
    ls0 += __shfl_xor_sync(0xffffffffu, ls0, 1);
    ls0 += __shfl_xor_sync(0xffffffffu, ls0, 2);
    ls1 += __shfl_xor_sync(0xffffffffu, ls1, 1);
    ls1 += __shfl_xor_sync(0xffffffffu, ls1, 2);

    // ---- normalize Y, pack into fp16 W-conv A-fragments (k = channel) ----
    uint32_t yf[8][4];
    {
        float rv0 = 1.f / ls0, rv1 = 1.f / ls1;
        #pragma unroll
        for (int n = 0; n < 16; n++) {
            int kk = n >> 1, e = (n & 1) * 2;
            yf[kk][e]     = pkh2(yacc[n][0] * rv0, yacc[n][1] * rv0);
            yf[kk][e + 1] = pkh2(yacc[n][2] * rv1, yacc[n][3] * rv1);
        }
    }

    // ---- WY = W_w @ Y + W_b : fp16 single term, two 128-channel halves ----
    const uint32_t bW = sb + SM_WB + (uint32_t)(bn * SQ + bk);
    float* WYb = g_WY + (size_t)b * CIN * NPOS + q0;

    #pragma unroll 1
    for (int h = 0; h < 2; h++) {
        __syncthreads();   // K/G reads done (h=0) / prev W reads done (h=1)
        const __half* wsrc = g_Whalf + (size_t)h * 128 * CI;
        for (int i = t; i < 2048; i += 256) {
            int r = i >> 4, c16 = i & 15;
            *(uint4*)(smem + SM_WB + (uint32_t)(r * SQ + c16 * 16)) =
                *(const uint4*)(wsrc + (size_t)r * CI + c16 * 8);
        }
        __syncthreads();

        float wacc[16][4];
        #pragma unroll
        for (int n = 0; n < 16; n++)
            #pragma unroll
            for (int j = 0; j < 4; j++) wacc[n][j] = 0.f;

        #pragma unroll
        for (int kk = 0; kk < 8; kk++) {
            #pragma unroll
            for (int np = 0; np < 8; np++) {
                uint32_t bh[4];
                ldsm4(bh, bW + np * (16 * SQ) + kk * 32);
                mma16816h(wacc[2 * np],     yf[kk], bh[0], bh[1]);
                mma16816h(wacc[2 * np + 1], yf[kk], bh[2], bh[3]);
            }
        }

        #pragma unroll
        for (int n = 0; n < 16; n++) {
            int o = h * 128 + 8 * n + 2 * tc;
            float b0 = __ldg(&W_b[o]);
            float b1 = __ldg(&W_b[o + 1]);
            int r0 = 16 * w + g;
            WYb[(size_t)o * NPOS + r0]           = wacc[n][0] + b0;
            WYb[(size_t)(o + 1) * NPOS + r0]     = wacc[n][1] + b1;
            WYb[(size_t)o * NPOS + r0 + 8]       = wacc[n][2] + b0;
            WYb[(size_t)(o + 1) * NPOS + r0 + 8] = wacc[n][3] + b1;
        }
    }
}

// =================================================================
// K3: BN statistics — partial pass + finalize
// =================================================================
__global__ __launch_bounds__(256) void stats_part_kernel()
{
    const int c = blockIdx.x;
    const int s = blockIdx.y;
    const int t = threadIdx.x;
    float sm = 0.f, ss = 0.f;
    for (int b = 2 * s; b < 2 * s + 2; b++) {
        const float* p = g_WY + ((size_t)b * CIN + c) * NPOS;
        for (int i = t; i < NPOS / 4; i += 256) {
            float4 v = *(const float4*)&p[4 * i];
            sm += v.x + v.y + v.z + v.w;
            ss += v.x * v.x + v.y * v.y + v.z * v.z + v.w * v.w;
        }
    }
    __shared__ float rs[256], rss[256];
    rs[t] = sm; rss[t] = ss;
    __syncthreads();
    for (int o = 128; o > 0; o >>= 1) {
        if (t < o) { rs[t] += rs[t + o]; rss[t] += rss[t + o]; }
        __syncthreads();
    }
    if (t == 0) {
        g_ps[s * CIN + c]  = rs[0];
        g_pss[s * CIN + c] = rss[0];
    }
}

__global__ __launch_bounds__(256) void stats_fin_kernel()
{
    const int c = threadIdx.x;
    float sm = g_ps[c] + g_ps[CIN + c] + g_ps[2 * CIN + c] + g_ps[3 * CIN + c];
    float ss = g_pss[c] + g_pss[CIN + c] + g_pss[2 * CIN + c] + g_pss[3 * CIN + c];
    const float inv = 1.f / (float)(BATCH * NPOS);
    float mean = sm * inv;
    float var  = ss * inv - mean * mean;
    g_mean[c] = mean;
    g_rstd[c] = rsqrtf(var + 1e-5f);
}

// =================================================================
// K4: z = (wy - mean)*rstd*gamma + beta + x
// =================================================================
__global__ __launch_bounds__(256) void final_kernel(
    const float* __restrict__ x,
    const float* __restrict__ gamma, const float* __restrict__ beta,
    float* __restrict__ z)
{
    size_t i4 = (size_t)blockIdx.x * 256 + threadIdx.x;
    size_t i  = i4 * 4;
    int c = (int)((i >> 12) & 255);
    float m = g_mean[c], r = g_rstd[c], ga = gamma[c], be = beta[c];
    float4 wy = *(const float4*)&g_WY[i];
    float4 xv = *(const float4*)&x[i];
    float4 o;
    o.x = (wy.x - m) * r * ga + be + xv.x;
    o.y = (wy.y - m) * r * ga + be + xv.y;
    o.z = (wy.z - m) * r * ga + be + xv.z;
    o.w = (wy.w - m) * r * ga + be + xv.w;
    *(float4*)&z[i] = o;
}

// =================================================================
extern "C" void kernel_launch(void* const* d_in, const int* in_sizes, int n_in,
                              void* d_out, int out_size)
{
    const float* x       = (const float*)d_in[0];
    const float* g_w     = (const float*)d_in[1];
    const float* g_b     = (const float*)d_in[2];
    const float* theta_w = (const float*)d_in[3];
    const float* theta_b = (const float*)d_in[4];
    const float* phi_w   = (const float*)d_in[5];
    const float* phi_b   = (const float*)d_in[6];
    const float* W_w     = (const float*)d_in[7];
    const float* W_b     = (const float*)d_in[8];
    const float* bn_g    = (const float*)d_in[9];
    const float* bn_b    = (const float*)d_in[10];
    float* z = (float*)d_out;

    cudaFuncSetAttribute(proj_npos_kernel, cudaFuncAttributeMaxDynamicSharedMemorySize, PJ_SMEM);
    cudaFuncSetAttribute(proj_chan_kernel, cudaFuncAttributeMaxDynamicSharedMemorySize, PG_SMEM);
    cudaFuncSetAttribute(attn_mma_kernel,  cudaFuncAttributeMaxDynamicSharedMemorySize, SMEM_BYTES);

    split_x_kernel<<<8192, 256>>>(x);
    split_wts_kernel<<<512, 256>>>(theta_w, phi_w, g_w, W_w);
    proj_npos_kernel<<<dim3(32, 8), 256, PJ_SMEM>>>(theta_b, phi_b);
    proj_chan_kernel<<<dim3(32, 8), 256, PG_SMEM>>>(g_b);
    attn_mma_kernel<<<dim3(32, 8), 256, SMEM_BYTES>>>(W_b);
    stats_part_kernel<<<dim3(256, 4), 256>>>();
    stats_fin_kernel<<<1, 256>>>();
    final_kernel<<<8192, 256>>>(x, bn_g, bn_b, z);
}